// round 9
// baseline (speedup 1.0000x reference)
#include <cuda_runtime.h>
#include <cuda_fp16.h>

// Problem constants (fixed by the dataset)
#define NN   100000
#define EE   1600000
#define DINK 128
#define HH   64
#define GGR  512

#define SCAN_B  512
#define SCAN_NB ((NN + SCAN_B - 1) / SCAN_B)   // 196

// Scratch (no allocations allowed -> __device__ globals)
__device__ float  g_p   [NN * HH];    // ping buffer (projected feats, fp32)
__device__ float  g_h   [NN * HH];    // pong buffer
__device__ __half g_ph_a[NN * HH];    // fp16 copy of p (ping)  -- gather source
__device__ __half g_ph_b[NN * HH];    // fp16 copy of p (pong)
__device__ float  g_pool[GGR * HH];   // graph pooling
__device__ int    g_deg [NN];         // degree, then CSR cursor
__device__ int    g_rowptr[NN + 1];
__device__ int    g_csr [EE];         // src list grouped by dst
__device__ int    g_bsums[SCAN_NB];

// ---------------------------------------------------------------------------
__device__ __forceinline__ void red4(float* a, float4 v) {
    asm volatile("red.global.add.v4.f32 [%0], {%1,%2,%3,%4};"
                 :: "l"(a), "f"(v.x), "f"(v.y), "f"(v.z), "f"(v.w)
                 : "memory");
}
__device__ __forceinline__ float4 f4zero() { return make_float4(0.f,0.f,0.f,0.f); }

__device__ __forceinline__ float4 ld_half4(const __half* a) {
    uint2 raw = *(const uint2*)a;
    float2 f0 = __half22float2(*reinterpret_cast<const __half2*>(&raw.x));
    float2 f1 = __half22float2(*reinterpret_cast<const __half2*>(&raw.y));
    return make_float4(f0.x, f0.y, f1.x, f1.y);
}
__device__ __forceinline__ void st_half4(__half* a, float4 v) {
    __half2 h0 = __floats2half2_rn(v.x, v.y);
    __half2 h1 = __floats2half2_rn(v.z, v.w);
    uint2 raw;
    raw.x = *reinterpret_cast<unsigned*>(&h0);
    raw.y = *reinterpret_cast<unsigned*>(&h1);
    *(uint2*)a = raw;
}

// ---------------------------------------------------------------------------
// CSR build: memset(deg) -> hist -> scan1/2/3 -> scatter
// ---------------------------------------------------------------------------
__global__ void hist_kernel(const int4* __restrict__ dst4) {
    int e = blockIdx.x * blockDim.x + threadIdx.x;
    if (e < EE / 4) {
        int4 d = __ldg(dst4 + e);
        atomicAdd(&g_deg[d.x], 1);
        atomicAdd(&g_deg[d.y], 1);
        atomicAdd(&g_deg[d.z], 1);
        atomicAdd(&g_deg[d.w], 1);
    }
}

__global__ void scan1_kernel() {        // block-local exclusive scan of deg
    __shared__ int s[2][SCAN_B];
    int t = threadIdx.x;
    int i = blockIdx.x * SCAN_B + t;
    int v = (i < NN) ? g_deg[i] : 0;
    int pin = 0;
    s[0][t] = v;
    __syncthreads();
#pragma unroll
    for (int off = 1; off < SCAN_B; off <<= 1) {
        int x = s[pin][t];
        if (t >= off) x += s[pin][t - off];
        pin ^= 1;
        s[pin][t] = x;
        __syncthreads();
    }
    int incl = s[pin][t];
    if (i < NN) g_rowptr[i] = incl - v;            // exclusive prefix
    if (t == SCAN_B - 1) g_bsums[blockIdx.x] = incl;
}

__global__ void scan2_kernel() {        // parallel exclusive scan of 196 sums
    __shared__ int s[2][256];
    int t = threadIdx.x;
    int v = (t < SCAN_NB) ? g_bsums[t] : 0;
    int pin = 0;
    s[0][t] = v;
    __syncthreads();
#pragma unroll
    for (int off = 1; off < 256; off <<= 1) {
        int x = s[pin][t];
        if (t >= off) x += s[pin][t - off];
        pin ^= 1;
        s[pin][t] = x;
        __syncthreads();
    }
    if (t < SCAN_NB) g_bsums[t] = s[pin][t] - v;   // exclusive
}

__global__ void scan3_kernel() {   // finalize rowptr, init cursor, zero pool
    int i = blockIdx.x * blockDim.x + threadIdx.x;
    if (i < NN) {
        int v = g_rowptr[i] + g_bsums[i / SCAN_B];
        g_rowptr[i] = v;
        g_deg[i]    = v;                // cursor for scatter
    }
    if (i < GGR * HH) g_pool[i] = 0.f;
    if (i == 0) g_rowptr[NN] = EE;
}

__global__ void scatter_kernel(const int4* __restrict__ src4,
                               const int4* __restrict__ dst4) {
    int e = blockIdx.x * blockDim.x + threadIdx.x;
    if (e < EE / 4) {
        int4 s = __ldg(src4 + e);
        int4 d = __ldg(dst4 + e);
        g_csr[atomicAdd(&g_deg[d.x], 1)] = s.x;
        g_csr[atomicAdd(&g_deg[d.y], 1)] = s.y;
        g_csr[atomicAdd(&g_deg[d.z], 1)] = s.z;
        g_csr[atomicAdd(&g_deg[d.w], 1)] = s.w;
    }
}

// ---------------------------------------------------------------------------
// 64-wide GEMM inner product, 4x4 register tile, a read as float4 along k.
// ASTR=68 -> row stride 272B: float4-aligned, tr=0/1 rows 16 banks apart.
// ---------------------------------------------------------------------------
#define ASTRD 68

__device__ __forceinline__ void mm64_f4(const float* __restrict__ As,
                                        const float* __restrict__ Ws,
                                        int tr, int tc, float4 acc[4]) {
#pragma unroll
    for (int k4 = 0; k4 < 64; k4 += 4) {
        float4 a[4];
#pragma unroll
        for (int r = 0; r < 4; r++)
            a[r] = *(const float4*)(As + (tr * 4 + r) * ASTRD + k4);
#pragma unroll
        for (int i = 0; i < 4; i++) {
            float4 w = *(const float4*)(Ws + (k4 + i) * 64 + tc * 4);
#pragma unroll
            for (int r = 0; r < 4; r++) {
                float av = (i == 0) ? a[r].x : (i == 1) ? a[r].y
                         : (i == 2) ? a[r].z : a[r].w;
                acc[r].x += av * w.x; acc[r].y += av * w.y;
                acc[r].z += av * w.z; acc[r].w += av * w.w;
            }
        }
    }
}

// ---------------------------------------------------------------------------
// Plain GEMM  C[nrows x 64] = A[nrows x K] @ W[K x 64]  (+bias, +relu opts)
// HALF_AUX: also store fp16 copy of C (gather source for the next layer).
// ---------------------------------------------------------------------------
template <int K, bool POST_BIAS, bool POST_RELU, bool HALF_AUX>
__global__ __launch_bounds__(256) void gemm64(
        const float* __restrict__ A, const float* __restrict__ W,
        const float* __restrict__ bpost, float* __restrict__ C,
        __half* __restrict__ Ch, int nrows) {
    __shared__ float Ws[64 * 64];
    __shared__ float As[64 * ASTRD];

    const int tid  = threadIdx.x;
    const int row0 = blockIdx.x * 64;
    const int tc   = tid & 15;
    const int tr   = tid >> 4;

    float4 acc[4];
#pragma unroll
    for (int r = 0; r < 4; r++) acc[r] = f4zero();

    for (int kb = 0; kb < K; kb += 64) {
        for (int i = tid; i < 64 * 64 / 4; i += 256)
            ((float4*)Ws)[i] = ((const float4*)(W + (size_t)kb * 64))[i];
        for (int i = tid; i < 64 * 64 / 4; i += 256) {
            int r  = i / 16;
            int kk = (i % 16) * 4;
            int row = row0 + r;
            float4 v = f4zero();
            if (row < nrows) v = *(const float4*)(A + (size_t)row * K + kb + kk);
            *(float4*)(As + r * ASTRD + kk) = v;
        }
        __syncthreads();
        mm64_f4(As, Ws, tr, tc, acc);
        __syncthreads();
    }

    float4 bp = f4zero();
    if constexpr (POST_BIAS) bp = *(const float4*)(bpost + tc * 4);
#pragma unroll
    for (int r = 0; r < 4; r++) {
        int row = row0 + tr * 4 + r;
        if (row < nrows) {
            float4 o = acc[r];
            if constexpr (POST_BIAS) {
                o.x += bp.x; o.y += bp.y; o.z += bp.z; o.w += bp.w;
            }
            if constexpr (POST_RELU) {
                o.x = fmaxf(o.x, 0.f); o.y = fmaxf(o.y, 0.f);
                o.z = fmaxf(o.z, 0.f); o.w = fmaxf(o.w, 0.f);
            }
            *(float4*)(C + (size_t)row * 64 + tc * 4) = o;
            if constexpr (HALF_AUX)
                st_half4(Ch + (size_t)row * 64 + tc * 4, o);
        }
    }
}

// ---------------------------------------------------------------------------
// Fused GIN layer (64-dim), 64 rows/block, 4x4 register tiles:
//   phase1: As[r] = relu( p[r] + sum_{s in N(r)} ph[s] + b1 )
//           (neighbors gathered from the fp16 copy: half the L2 bytes;
//            self term from fp32 p)
//   phase2: H     = relu( As @ W2 + b2 )                        (regs)
//   phase3: p_out = H @ W1n  (+ fp16 copy)  |  LAST: pool[batch[r]] += H[r]
// ---------------------------------------------------------------------------
template <bool LAST>
__global__ __launch_bounds__(256) void gin_fused(
        const float*  __restrict__ p,
        const __half* __restrict__ ph,
        const float*  __restrict__ b1,
        const float*  __restrict__ W2,
        const float*  __restrict__ b2,
        const float*  __restrict__ W1n,
        float*  __restrict__ p_out,
        __half* __restrict__ ph_out,
        const int* __restrict__ batch,
        float* __restrict__ pool) {
    __shared__ float Ws[64 * 64];
    __shared__ float As[64 * ASTRD];

    const int tid  = threadIdx.x;
    const int row0 = blockIdx.x * 64;

    // stage W2 early (gather __syncthreads covers it)
    for (int i = tid; i < 64 * 64 / 4; i += 256)
        ((float4*)Ws)[i] = ((const float4*)W2)[i];

    // ---- phase 1: CSR gather (fp16) + self (fp32) + b1 + relu into As ----
    {
        const int grp  = tid >> 4;        // 16 groups of 16 threads
        const int part = (tid & 15) * 4;  // float4 lane within the 64-dim row
        float4 b1v = *(const float4*)(b1 + part);
#pragma unroll
        for (int rr = 0; rr < 4; rr++) {
            int r   = grp * 4 + rr;
            int row = row0 + r;
            float4 acc = f4zero();
            if (row < NN) {
                int beg = __ldg(g_rowptr + row);
                int end = __ldg(g_rowptr + row + 1);
                int j = beg;
                for (; j + 4 <= end; j += 4) {     // 4-wide for MLP
                    int s0 = __ldg(g_csr + j);
                    int s1 = __ldg(g_csr + j + 1);
                    int s2 = __ldg(g_csr + j + 2);
                    int s3 = __ldg(g_csr + j + 3);
                    float4 v0 = ld_half4(ph + (size_t)s0 * 64 + part);
                    float4 v1 = ld_half4(ph + (size_t)s1 * 64 + part);
                    float4 v2 = ld_half4(ph + (size_t)s2 * 64 + part);
                    float4 v3 = ld_half4(ph + (size_t)s3 * 64 + part);
                    acc.x += (v0.x + v1.x) + (v2.x + v3.x);
                    acc.y += (v0.y + v1.y) + (v2.y + v3.y);
                    acc.z += (v0.z + v1.z) + (v2.z + v3.z);
                    acc.w += (v0.w + v1.w) + (v2.w + v3.w);
                }
                for (; j < end; j++) {
                    int s = __ldg(g_csr + j);
                    float4 v = ld_half4(ph + (size_t)s * 64 + part);
                    acc.x += v.x; acc.y += v.y; acc.z += v.z; acc.w += v.w;
                }
                float4 self = *(const float4*)(p + (size_t)row * 64 + part);
                acc.x = fmaxf(acc.x + self.x + b1v.x, 0.f);
                acc.y = fmaxf(acc.y + self.y + b1v.y, 0.f);
                acc.z = fmaxf(acc.z + self.z + b1v.z, 0.f);
                acc.w = fmaxf(acc.w + self.w + b1v.w, 0.f);
            }
            *(float4*)(As + r * ASTRD + part) = acc;
        }
    }
    __syncthreads();

    const int tc = tid & 15;
    const int tr = tid >> 4;

    // ---- phase 2: H = relu(As @ W2 + b2) ----
    float4 acc[4];
#pragma unroll
    for (int r = 0; r < 4; r++) acc[r] = f4zero();
    mm64_f4(As, Ws, tr, tc, acc);

    float4 b2v = *(const float4*)(b2 + tc * 4);
#pragma unroll
    for (int r = 0; r < 4; r++) {
        acc[r].x = fmaxf(acc[r].x + b2v.x, 0.f);
        acc[r].y = fmaxf(acc[r].y + b2v.y, 0.f);
        acc[r].z = fmaxf(acc[r].z + b2v.z, 0.f);
        acc[r].w = fmaxf(acc[r].w + b2v.w, 0.f);
    }

    if constexpr (LAST) {
        // ---- pool epilogue: pool[batch[row]] += H[row], run-combined ----
        int b_prev = -1;
        float4 run = f4zero();
#pragma unroll
        for (int r = 0; r < 4; r++) {
            int row = row0 + tr * 4 + r;
            if (row < NN) {
                int b = __ldg(batch + row);
                if (b == b_prev) {
                    run.x += acc[r].x; run.y += acc[r].y;
                    run.z += acc[r].z; run.w += acc[r].w;
                } else {
                    if (b_prev >= 0)
                        red4(pool + (size_t)b_prev * 64 + tc * 4, run);
                    b_prev = b; run = acc[r];
                }
            }
        }
        if (b_prev >= 0) red4(pool + (size_t)b_prev * 64 + tc * 4, run);
    } else {
        // ---- phase 3: p_out = H @ W1n ----
        __syncthreads();                      // phase-2 As/Ws reads done
#pragma unroll
        for (int r = 0; r < 4; r++)           // H -> As (reuse)
            *(float4*)(As + (tr * 4 + r) * ASTRD + tc * 4) = acc[r];
        for (int i = tid; i < 64 * 64 / 4; i += 256)
            ((float4*)Ws)[i] = ((const float4*)W1n)[i];
        __syncthreads();

        float4 acc2[4];
#pragma unroll
        for (int r = 0; r < 4; r++) acc2[r] = f4zero();
        mm64_f4(As, Ws, tr, tc, acc2);
#pragma unroll
        for (int r = 0; r < 4; r++) {
            int row = row0 + tr * 4 + r;
            if (row < NN) {
                *(float4*)(p_out + (size_t)row * 64 + tc * 4) = acc2[r];
                st_half4(ph_out + (size_t)row * 64 + tc * 4, acc2[r]);
            }
        }
    }
}

// out[512 x 16] = t[512 x 64] @ mw2[64 x 16] + mb2
__global__ void readout2(const float* __restrict__ t,
                         const float* __restrict__ mw2,
                         const float* __restrict__ mb2,
                         float* __restrict__ out) {
    __shared__ float Ws[64 * 16];
    int tid = threadIdx.x;
    for (int i = tid; i < 64 * 16 / 4; i += blockDim.x)
        ((float4*)Ws)[i] = ((const float4*)mw2)[i];
    __syncthreads();

    int idx = blockIdx.x * blockDim.x + tid;
    if (idx >= GGR * 16) return;
    int g = idx >> 4, c = idx & 15;
    float s = __ldg(mb2 + c);
    const float* tr_ = t + (size_t)g * 64;
#pragma unroll
    for (int k = 0; k < 64; k++) s += tr_[k] * Ws[k * 16 + c];
    out[idx] = s;
}

// ---------------------------------------------------------------------------
extern "C" void kernel_launch(void* const* d_in, const int* in_sizes, int n_in,
                              void* d_out, int out_size) {
    const float* x     = (const float*)d_in[0];
    const int*   ei    = (const int*)d_in[1];
    const int*   batch = (const int*)d_in[2];
    const float* w1_0  = (const float*)d_in[3];
    const float* b1_0  = (const float*)d_in[4];
    const float* w2_0  = (const float*)d_in[5];
    const float* b2_0  = (const float*)d_in[6];
    const float* w1_r  = (const float*)d_in[7];
    const float* b1_r  = (const float*)d_in[8];
    const float* w2_r  = (const float*)d_in[9];
    const float* b2_r  = (const float*)d_in[10];
    const float* mw1   = (const float*)d_in[11];
    const float* mb1   = (const float*)d_in[12];
    const float* mw2   = (const float*)d_in[13];
    const float* mb2   = (const float*)d_in[14];

    const int* src = ei;
    const int* dst = ei + EE;

    float *p, *h, *pool;
    __half *pha, *phb;
    int *deg;
    cudaGetSymbolAddress((void**)&p,    g_p);
    cudaGetSymbolAddress((void**)&h,    g_h);
    cudaGetSymbolAddress((void**)&pha,  g_ph_a);
    cudaGetSymbolAddress((void**)&phb,  g_ph_b);
    cudaGetSymbolAddress((void**)&pool, g_pool);
    cudaGetSymbolAddress((void**)&deg,  g_deg);

    const int gemm_blocks  = (NN + 63) / 64;        // 1563
    const int edge4_blocks = (EE / 4 + 255) / 256;  // 1563
    const int node_blocks  = (NN + 255) / 256;      // 391

    // --- CSR build ---
    cudaMemsetAsync(deg, 0, NN * sizeof(int));
    hist_kernel<<<edge4_blocks, 256>>>((const int4*)dst);
    scan1_kernel<<<SCAN_NB, SCAN_B>>>();
    scan2_kernel<<<1, 256>>>();
    scan3_kernel<<<node_blocks, 256>>>();           // also zeroes pool
    scatter_kernel<<<edge4_blocks, 256>>>((const int4*)src, (const int4*)dst);

    // --- input projection: p = x @ w1_0  (K=128), + fp16 copy ---
    gemm64<DINK, false, false, true><<<gemm_blocks, 256>>>(
        x, w1_0, nullptr, p, pha, NN);

    // --- 5 fused GIN layers, ping-ponging (p,pha) <-> (h,phb) ---
    gin_fused<false><<<gemm_blocks, 256>>>(p, pha, b1_0, w2_0, b2_0,
                                           w1_r + 0 * HH * HH, h, phb,
                                           nullptr, nullptr);
    gin_fused<false><<<gemm_blocks, 256>>>(h, phb, b1_r + 0 * HH,
                                           w2_r + 0 * HH * HH, b2_r + 0 * HH,
                                           w1_r + 1 * HH * HH, p, pha,
                                           nullptr, nullptr);
    gin_fused<false><<<gemm_blocks, 256>>>(p, pha, b1_r + 1 * HH,
                                           w2_r + 1 * HH * HH, b2_r + 1 * HH,
                                           w1_r + 2 * HH * HH, h, phb,
                                           nullptr, nullptr);
    gin_fused<false><<<gemm_blocks, 256>>>(h, phb, b1_r + 2 * HH,
                                           w2_r + 2 * HH * HH, b2_r + 2 * HH,
                                           w1_r + 3 * HH * HH, p, pha,
                                           nullptr, nullptr);
    gin_fused<true ><<<gemm_blocks, 256>>>(p, pha, b1_r + 3 * HH,
                                           w2_r + 3 * HH * HH, b2_r + 3 * HH,
                                           nullptr, nullptr, nullptr,
                                           batch, pool);

    // --- readout: relu(pool @ mw1 + mb1) @ mw2 + mb2 ---
    gemm64<HH, true, true, false><<<(GGR + 63) / 64, 256>>>(
        pool, mw1, mb1, h, nullptr, GGR);
    readout2<<<(GGR * 16 + 255) / 256, 256>>>(h, mw2, mb2, (float*)d_out);
}

// round 11
// speedup vs baseline: 1.1624x; 1.1624x over previous
#include <cuda_runtime.h>
#include <cuda_fp16.h>
#include <cstdint>

// Problem constants (fixed by the dataset)
#define NN   100000
#define EE   1600000
#define DINK 128
#define HH   64
#define GGR  512

#define SCAN_B  512
#define SCAN_NB ((NN + SCAN_B - 1) / SCAN_B)   // 196

// Scratch (no allocations allowed -> __device__ globals)
__device__ float  g_p   [NN * HH];    // ping fp32 features
__device__ float  g_h   [NN * HH];    // pong fp32 features / readout temp
__device__ __half g_pha [NN * HH];    // fp16 copy (ping) -- gather source
__device__ __half g_phb [NN * HH];    // fp16 copy (pong)
__device__ float  g_pool[GGR * HH];
__device__ int    g_deg [NN];
__device__ int    g_rowptr[NN + 1];
__device__ int    g_csr [EE];
__device__ int    g_bsums[SCAN_NB];
// fp16 weights transposed to [n][k] (9 mats of 64x64):
// 0 = w2_0, 1..4 = w2_r[0..3], 5..8 = w1_r[0..3]
__device__ __half g_wT[9 * 64 * 64];

// ---------------------------------------------------------------------------
__device__ __forceinline__ void red4(float* a, float4 v) {
    asm volatile("red.global.add.v4.f32 [%0], {%1,%2,%3,%4};"
                 :: "l"(a), "f"(v.x), "f"(v.y), "f"(v.z), "f"(v.w)
                 : "memory");
}
__device__ __forceinline__ float4 f4zero() { return make_float4(0.f,0.f,0.f,0.f); }

__device__ __forceinline__ float4 ld_half4(const __half* a) {
    uint2 raw = *(const uint2*)a;
    float2 f0 = __half22float2(*reinterpret_cast<const __half2*>(&raw.x));
    float2 f1 = __half22float2(*reinterpret_cast<const __half2*>(&raw.y));
    return make_float4(f0.x, f0.y, f1.x, f1.y);
}
__device__ __forceinline__ void st_half4(__half* a, float4 v) {
    __half2 h0 = __floats2half2_rn(v.x, v.y);
    __half2 h1 = __floats2half2_rn(v.z, v.w);
    uint2 raw;
    raw.x = *reinterpret_cast<unsigned*>(&h0);
    raw.y = *reinterpret_cast<unsigned*>(&h1);
    *(uint2*)a = raw;
}

// m16n8k16 fp16 MMA, f32 accumulators (sm_80+ PTX; legal on bare sm_103)
#define MMA16816(c, a0, a1, a2, a3, b0, b1) \
    asm volatile("mma.sync.aligned.m16n8k16.row.col.f32.f16.f16.f32 " \
        "{%0,%1,%2,%3}, {%4,%5,%6,%7}, {%8,%9}, {%0,%1,%2,%3};" \
        : "+f"((c)[0]), "+f"((c)[1]), "+f"((c)[2]), "+f"((c)[3]) \
        : "r"(a0), "r"(a1), "r"(a2), "r"(a3), "r"(b0), "r"(b1))

// ---------------------------------------------------------------------------
// CSR build: memset(deg) -> hist -> scan1/2/3 -> scatter
// ---------------------------------------------------------------------------
__global__ void hist_kernel(const int4* __restrict__ dst4) {
    int e = blockIdx.x * blockDim.x + threadIdx.x;
    if (e < EE / 4) {
        int4 d = __ldg(dst4 + e);
        atomicAdd(&g_deg[d.x], 1);
        atomicAdd(&g_deg[d.y], 1);
        atomicAdd(&g_deg[d.z], 1);
        atomicAdd(&g_deg[d.w], 1);
    }
}

__global__ void scan1_kernel() {
    __shared__ int s[2][SCAN_B];
    int t = threadIdx.x;
    int i = blockIdx.x * SCAN_B + t;
    int v = (i < NN) ? g_deg[i] : 0;
    int pin = 0;
    s[0][t] = v;
    __syncthreads();
#pragma unroll
    for (int off = 1; off < SCAN_B; off <<= 1) {
        int x = s[pin][t];
        if (t >= off) x += s[pin][t - off];
        pin ^= 1;
        s[pin][t] = x;
        __syncthreads();
    }
    int incl = s[pin][t];
    if (i < NN) g_rowptr[i] = incl - v;
    if (t == SCAN_B - 1) g_bsums[blockIdx.x] = incl;
}

__global__ void scan2_kernel() {
    __shared__ int s[2][256];
    int t = threadIdx.x;
    int v = (t < SCAN_NB) ? g_bsums[t] : 0;
    int pin = 0;
    s[0][t] = v;
    __syncthreads();
#pragma unroll
    for (int off = 1; off < 256; off <<= 1) {
        int x = s[pin][t];
        if (t >= off) x += s[pin][t - off];
        pin ^= 1;
        s[pin][t] = x;
        __syncthreads();
    }
    if (t < SCAN_NB) g_bsums[t] = s[pin][t] - v;
}

__global__ void scan3_kernel() {   // finalize rowptr, init cursor, zero pool
    int i = blockIdx.x * blockDim.x + threadIdx.x;
    if (i < NN) {
        int v = g_rowptr[i] + g_bsums[i / SCAN_B];
        g_rowptr[i] = v;
        g_deg[i]    = v;
    }
    if (i < GGR * HH) g_pool[i] = 0.f;
    if (i == 0) g_rowptr[NN] = EE;
}

__global__ void scatter_kernel(const int4* __restrict__ src4,
                               const int4* __restrict__ dst4) {
    int e = blockIdx.x * blockDim.x + threadIdx.x;
    if (e < EE / 4) {
        int4 s = __ldg(src4 + e);
        int4 d = __ldg(dst4 + e);
        g_csr[atomicAdd(&g_deg[d.x], 1)] = s.x;
        g_csr[atomicAdd(&g_deg[d.y], 1)] = s.y;
        g_csr[atomicAdd(&g_deg[d.z], 1)] = s.z;
        g_csr[atomicAdd(&g_deg[d.w], 1)] = s.w;
    }
}

// ---------------------------------------------------------------------------
// Pre-transpose weights to fp16 [n][k] (B col-major for mma row.col)
// ---------------------------------------------------------------------------
__global__ void prep_weights(const float* __restrict__ w2_0,
                             const float* __restrict__ w2_r,
                             const float* __restrict__ w1_r) {
    int idx = blockIdx.x * blockDim.x + threadIdx.x;
    if (idx >= 9 * 4096) return;
    int m = idx >> 12, e = idx & 4095;
    int n = e >> 6, k = e & 63;
    const float* src = (m == 0) ? w2_0
                     : (m <= 4) ? (w2_r + (size_t)(m - 1) * 4096)
                                : (w1_r + (size_t)(m - 5) * 4096);
    g_wT[m * 4096 + n * 64 + k] = __float2half(src[k * 64 + n]);
}

// ---------------------------------------------------------------------------
// fp32 FFMA GEMM (projection K=128, readout) -- proven path
// ---------------------------------------------------------------------------
#define ASTRD 68
__device__ __forceinline__ void mm64_f4(const float* __restrict__ As,
                                        const float* __restrict__ Ws,
                                        int tr, int tc, float4 acc[4]) {
#pragma unroll
    for (int k4 = 0; k4 < 64; k4 += 4) {
        float4 a[4];
#pragma unroll
        for (int r = 0; r < 4; r++)
            a[r] = *(const float4*)(As + (tr * 4 + r) * ASTRD + k4);
#pragma unroll
        for (int i = 0; i < 4; i++) {
            float4 w = *(const float4*)(Ws + (k4 + i) * 64 + tc * 4);
#pragma unroll
            for (int r = 0; r < 4; r++) {
                float av = (i == 0) ? a[r].x : (i == 1) ? a[r].y
                         : (i == 2) ? a[r].z : a[r].w;
                acc[r].x += av * w.x; acc[r].y += av * w.y;
                acc[r].z += av * w.z; acc[r].w += av * w.w;
            }
        }
    }
}

template <int K, bool POST_BIAS, bool POST_RELU, bool HALF_AUX>
__global__ __launch_bounds__(256) void gemm64(
        const float* __restrict__ A, const float* __restrict__ W,
        const float* __restrict__ bpost, float* __restrict__ C,
        __half* __restrict__ Ch, int nrows) {
    __shared__ float Ws[64 * 64];
    __shared__ float As[64 * ASTRD];

    const int tid  = threadIdx.x;
    const int row0 = blockIdx.x * 64;
    const int tc   = tid & 15;
    const int tr   = tid >> 4;

    float4 acc[4];
#pragma unroll
    for (int r = 0; r < 4; r++) acc[r] = f4zero();

    for (int kb = 0; kb < K; kb += 64) {
        for (int i = tid; i < 64 * 64 / 4; i += 256)
            ((float4*)Ws)[i] = ((const float4*)(W + (size_t)kb * 64))[i];
        for (int i = tid; i < 64 * 64 / 4; i += 256) {
            int r  = i / 16;
            int kk = (i % 16) * 4;
            int row = row0 + r;
            float4 v = f4zero();
            if (row < nrows) v = *(const float4*)(A + (size_t)row * K + kb + kk);
            *(float4*)(As + r * ASTRD + kk) = v;
        }
        __syncthreads();
        mm64_f4(As, Ws, tr, tc, acc);
        __syncthreads();
    }

    float4 bp = f4zero();
    if constexpr (POST_BIAS) bp = *(const float4*)(bpost + tc * 4);
#pragma unroll
    for (int r = 0; r < 4; r++) {
        int row = row0 + tr * 4 + r;
        if (row < nrows) {
            float4 o = acc[r];
            if constexpr (POST_BIAS) {
                o.x += bp.x; o.y += bp.y; o.z += bp.z; o.w += bp.w;
            }
            if constexpr (POST_RELU) {
                o.x = fmaxf(o.x, 0.f); o.y = fmaxf(o.y, 0.f);
                o.z = fmaxf(o.z, 0.f); o.w = fmaxf(o.w, 0.f);
            }
            *(float4*)(C + (size_t)row * 64 + tc * 4) = o;
            if constexpr (HALF_AUX)
                st_half4(Ch + (size_t)row * 64 + tc * 4, o);
        }
    }
}

// ---------------------------------------------------------------------------
// Fused GIN layer with HMMA (mma.sync m16n8k16). 128 rows/block, 8 warps.
//   phase1: z = relu(p_self + sum_N ph + b1) -> fp16 tile Ah[128][72]
//   MMA1:   warp w computes rows w*16..+15:  D = z @ W2^T
//   epi:    h = relu(D + b2) -> back into Ah (own rows; no cross-warp hazard)
//   MMA2:   D = h @ W1n^T -> p_out fp32 + fp16 copy
//   LAST:   pool[batch[row]] += h   (run-combined red4 from Ah)
// ---------------------------------------------------------------------------
#define APAD 72   // halves per row; pad makes all fragment LDS conflict-free

template <bool LAST>
__global__ __launch_bounds__(256) void gin_hmma(
        const float*  __restrict__ p,
        const __half* __restrict__ ph,
        const float*  __restrict__ b1,
        const float*  __restrict__ b2,
        int matW2, int matW1n,
        float*  __restrict__ p_out,
        __half* __restrict__ ph_out,
        const int* __restrict__ batch) {
    __shared__ __half Ah[128 * APAD];   // 18 KB
    __shared__ __half Bh[64 * APAD];    //  9 KB
    __shared__ float  s_b2[64];

    const int tid  = threadIdx.x;
    const int wid  = tid >> 5;
    const int lane = tid & 31;
    const int row0 = blockIdx.x * 128;

    // stage W2 -> Bh [n][k] (plain fp16, 16B chunks; row stride 144B = 9*16)
    {
        const __half* wsrc = g_wT + (size_t)matW2 * 4096;
        for (int i = tid; i < 64 * 8; i += 256) {
            int n = i >> 3, c = (i & 7) * 8;
            *(uint4*)(Bh + n * APAD + c) = *(const uint4*)(wsrc + n * 64 + c);
        }
    }
    if (tid < 64) s_b2[tid] = b2[tid];

    // ---- phase 1: CSR gather -> z -> fp16 tile ----
    {
        const int grp  = tid >> 4;        // 16 groups of 16 lanes, 8 rows each
        const int part = (tid & 15) * 4;  // element offset in 64-dim row
        float4 b1v = *(const float4*)(b1 + part);
        for (int rr = 0; rr < 8; rr++) {
            int r   = grp * 8 + rr;
            int row = row0 + r;
            float4 acc = f4zero();
            if (row < NN) {
                int beg = __ldg(g_rowptr + row);
                int end = __ldg(g_rowptr + row + 1);
                int j = beg;
                for (; j + 4 <= end; j += 4) {
                    int s0 = __ldg(g_csr + j);
                    int s1 = __ldg(g_csr + j + 1);
                    int s2 = __ldg(g_csr + j + 2);
                    int s3 = __ldg(g_csr + j + 3);
                    float4 v0 = ld_half4(ph + (size_t)s0 * 64 + part);
                    float4 v1 = ld_half4(ph + (size_t)s1 * 64 + part);
                    float4 v2 = ld_half4(ph + (size_t)s2 * 64 + part);
                    float4 v3 = ld_half4(ph + (size_t)s3 * 64 + part);
                    acc.x += (v0.x + v1.x) + (v2.x + v3.x);
                    acc.y += (v0.y + v1.y) + (v2.y + v3.y);
                    acc.z += (v0.z + v1.z) + (v2.z + v3.z);
                    acc.w += (v0.w + v1.w) + (v2.w + v3.w);
                }
                for (; j < end; j++) {
                    int s = __ldg(g_csr + j);
                    float4 v = ld_half4(ph + (size_t)s * 64 + part);
                    acc.x += v.x; acc.y += v.y; acc.z += v.z; acc.w += v.w;
                }
                float4 self = *(const float4*)(p + (size_t)row * 64 + part);
                acc.x = fmaxf(acc.x + self.x + b1v.x, 0.f);
                acc.y = fmaxf(acc.y + self.y + b1v.y, 0.f);
                acc.z = fmaxf(acc.z + self.z + b1v.z, 0.f);
                acc.w = fmaxf(acc.w + self.w + b1v.w, 0.f);
            }
            st_half4(Ah + r * APAD + part, acc);
        }
    }
    __syncthreads();

    // fragment coordinates for this lane
    const int mrow = wid * 16 + (lane >> 2);   // A/D row (first of pair)
    const int kx   = (lane & 3) * 2;           // k offset within k16 tile
    const int col  = (lane & 3) * 2;           // D col offset within n8 tile

    // ---- MMA1: D = z @ W2^T ----
    float c[8][4];
#pragma unroll
    for (int nt = 0; nt < 8; nt++)
#pragma unroll
        for (int i = 0; i < 4; i++) c[nt][i] = 0.f;

#pragma unroll
    for (int ks = 0; ks < 4; ks++) {
        const int kb = ks * 16 + kx;
        uint32_t a0 = *(const uint32_t*)(Ah + (size_t)mrow * APAD + kb);
        uint32_t a1 = *(const uint32_t*)(Ah + (size_t)(mrow + 8) * APAD + kb);
        uint32_t a2 = *(const uint32_t*)(Ah + (size_t)mrow * APAD + kb + 8);
        uint32_t a3 = *(const uint32_t*)(Ah + (size_t)(mrow + 8) * APAD + kb + 8);
#pragma unroll
        for (int nt = 0; nt < 8; nt++) {
            uint32_t b0 = *(const uint32_t*)(Bh + (size_t)(nt * 8 + (lane >> 2)) * APAD + kb);
            uint32_t b1r = *(const uint32_t*)(Bh + (size_t)(nt * 8 + (lane >> 2)) * APAD + kb + 8);
            MMA16816(c[nt], a0, a1, a2, a3, b0, b1r);
        }
    }

    // ---- epilogue: h = relu(D + b2) -> Ah (own rows) ----
#pragma unroll
    for (int nt = 0; nt < 8; nt++) {
        int n0 = nt * 8 + col;
        float bz0 = s_b2[n0], bz1 = s_b2[n0 + 1];
        __half2 h0 = __floats2half2_rn(fmaxf(c[nt][0] + bz0, 0.f),
                                       fmaxf(c[nt][1] + bz1, 0.f));
        __half2 h1 = __floats2half2_rn(fmaxf(c[nt][2] + bz0, 0.f),
                                       fmaxf(c[nt][3] + bz1, 0.f));
        *(uint32_t*)(Ah + (size_t)mrow * APAD + n0) =
            *reinterpret_cast<unsigned*>(&h0);
        *(uint32_t*)(Ah + (size_t)(mrow + 8) * APAD + n0) =
            *reinterpret_cast<unsigned*>(&h1);
    }
    __syncthreads();   // all warps done reading Bh + writing Ah

    if constexpr (LAST) {
        // ---- pool: pool[batch[row]] += h, run-combined over sorted batch ----
        const int grp  = tid >> 4;
        const int part = (tid & 15) * 4;
        int b_prev = -1;
        float4 run = f4zero();
        for (int rr = 0; rr < 8; rr++) {
            int r = grp * 8 + rr, row = row0 + r;
            if (row < NN) {
                float4 v = ld_half4(Ah + (size_t)r * APAD + part);
                int b = __ldg(batch + row);
                if (b == b_prev) {
                    run.x += v.x; run.y += v.y; run.z += v.z; run.w += v.w;
                } else {
                    if (b_prev >= 0)
                        red4(g_pool + (size_t)b_prev * 64 + part, run);
                    b_prev = b; run = v;
                }
            }
        }
        if (b_prev >= 0) red4(g_pool + (size_t)b_prev * 64 + part, run);
    } else {
        // ---- restage B with W1n, MMA2, store p_out ----
        {
            const __half* wsrc = g_wT + (size_t)matW1n * 4096;
            for (int i = tid; i < 64 * 8; i += 256) {
                int n = i >> 3, cc = (i & 7) * 8;
                *(uint4*)(Bh + n * APAD + cc) = *(const uint4*)(wsrc + n * 64 + cc);
            }
        }
        __syncthreads();

#pragma unroll
        for (int nt = 0; nt < 8; nt++)
#pragma unroll
            for (int i = 0; i < 4; i++) c[nt][i] = 0.f;

#pragma unroll
        for (int ks = 0; ks < 4; ks++) {
            const int kb = ks * 16 + kx;
            uint32_t a0 = *(const uint32_t*)(Ah + (size_t)mrow * APAD + kb);
            uint32_t a1 = *(const uint32_t*)(Ah + (size_t)(mrow + 8) * APAD + kb);
            uint32_t a2 = *(const uint32_t*)(Ah + (size_t)mrow * APAD + kb + 8);
            uint32_t a3 = *(const uint32_t*)(Ah + (size_t)(mrow + 8) * APAD + kb + 8);
#pragma unroll
            for (int nt = 0; nt < 8; nt++) {
                uint32_t b0 = *(const uint32_t*)(Bh + (size_t)(nt * 8 + (lane >> 2)) * APAD + kb);
                uint32_t b1r = *(const uint32_t*)(Bh + (size_t)(nt * 8 + (lane >> 2)) * APAD + kb + 8);
                MMA16816(c[nt], a0, a1, a2, a3, b0, b1r);
            }
        }

        const int rowA = row0 + mrow;
        const int rowB = rowA + 8;
#pragma unroll
        for (int nt = 0; nt < 8; nt++) {
            int n0 = nt * 8 + col;
            if (rowA < NN) {
                *(float2*)(p_out + (size_t)rowA * 64 + n0) =
                    make_float2(c[nt][0], c[nt][1]);
                __half2 hh = __floats2half2_rn(c[nt][0], c[nt][1]);
                *(uint32_t*)(ph_out + (size_t)rowA * 64 + n0) =
                    *reinterpret_cast<unsigned*>(&hh);
            }
            if (rowB < NN) {
                *(float2*)(p_out + (size_t)rowB * 64 + n0) =
                    make_float2(c[nt][2], c[nt][3]);
                __half2 hh = __floats2half2_rn(c[nt][2], c[nt][3]);
                *(uint32_t*)(ph_out + (size_t)rowB * 64 + n0) =
                    *reinterpret_cast<unsigned*>(&hh);
            }
        }
    }
}

// out[512 x 16] = t[512 x 64] @ mw2[64 x 16] + mb2
__global__ void readout2(const float* __restrict__ t,
                         const float* __restrict__ mw2,
                         const float* __restrict__ mb2,
                         float* __restrict__ out) {
    __shared__ float Ws[64 * 16];
    int tid = threadIdx.x;
    for (int i = tid; i < 64 * 16 / 4; i += blockDim.x)
        ((float4*)Ws)[i] = ((const float4*)mw2)[i];
    __syncthreads();

    int idx = blockIdx.x * blockDim.x + tid;
    if (idx >= GGR * 16) return;
    int g = idx >> 4, c = idx & 15;
    float s = __ldg(mb2 + c);
    const float* tr_ = t + (size_t)g * 64;
#pragma unroll
    for (int k = 0; k < 64; k++) s += tr_[k] * Ws[k * 16 + c];
    out[idx] = s;
}

// ---------------------------------------------------------------------------
extern "C" void kernel_launch(void* const* d_in, const int* in_sizes, int n_in,
                              void* d_out, int out_size) {
    const float* x     = (const float*)d_in[0];
    const int*   ei    = (const int*)d_in[1];
    const int*   batch = (const int*)d_in[2];
    const float* w1_0  = (const float*)d_in[3];
    const float* b1_0  = (const float*)d_in[4];
    const float* w2_0  = (const float*)d_in[5];
    const float* b2_0  = (const float*)d_in[6];
    const float* w1_r  = (const float*)d_in[7];
    const float* b1_r  = (const float*)d_in[8];
    const float* w2_r  = (const float*)d_in[9];
    const float* b2_r  = (const float*)d_in[10];
    const float* mw1   = (const float*)d_in[11];
    const float* mb1   = (const float*)d_in[12];
    const float* mw2   = (const float*)d_in[13];
    const float* mb2   = (const float*)d_in[14];

    const int* src = ei;
    const int* dst = ei + EE;

    float *p, *h, *pool;
    __half *pha, *phb;
    int *deg;
    cudaGetSymbolAddress((void**)&p,    g_p);
    cudaGetSymbolAddress((void**)&h,    g_h);
    cudaGetSymbolAddress((void**)&pha,  g_pha);
    cudaGetSymbolAddress((void**)&phb,  g_phb);
    cudaGetSymbolAddress((void**)&pool, g_pool);
    cudaGetSymbolAddress((void**)&deg,  g_deg);

    const int gemm_blocks  = (NN + 63) / 64;        // 1563
    const int mma_blocks   = (NN + 127) / 128;      // 782
    const int edge4_blocks = (EE / 4 + 255) / 256;  // 1563
    const int node_blocks  = (NN + 255) / 256;      // 391

    cudaMemsetAsync(deg, 0, NN * sizeof(int));                 // idx 0
    hist_kernel<<<edge4_blocks, 256>>>((const int4*)dst);      // idx 1
    scan1_kernel<<<SCAN_NB, SCAN_B>>>();                       // idx 2
    scan2_kernel<<<1, 256>>>();                                // idx 3
    scan3_kernel<<<node_blocks, 256>>>();                      // idx 4 (also zeroes pool)
    // projection at profile index 5 (no CSR dependency)
    gemm64<DINK, false, false, true><<<gemm_blocks, 256>>>(
        x, w1_0, nullptr, p, pha, NN);                         // idx 5 <- ncu
    scatter_kernel<<<edge4_blocks, 256>>>((const int4*)src, (const int4*)dst);
    prep_weights<<<(9 * 4096 + 255) / 256, 256>>>(w2_0, w2_r, w1_r);

    // --- 5 fused GIN layers (HMMA), ping-ponging (p,pha) <-> (h,phb) ---
    gin_hmma<false><<<mma_blocks, 256>>>(p, pha, b1_0,        b2_0,        0, 5,
                                         h, phb, nullptr);
    gin_hmma<false><<<mma_blocks, 256>>>(h, phb, b1_r + 0*HH, b2_r + 0*HH, 1, 6,
                                         p, pha, nullptr);
    gin_hmma<false><<<mma_blocks, 256>>>(p, pha, b1_r + 1*HH, b2_r + 1*HH, 2, 7,
                                         h, phb, nullptr);
    gin_hmma<false><<<mma_blocks, 256>>>(h, phb, b1_r + 2*HH, b2_r + 2*HH, 3, 8,
                                         p, pha, nullptr);
    gin_hmma<true ><<<mma_blocks, 256>>>(p, pha, b1_r + 3*HH, b2_r + 3*HH, 4, -1,
                                         nullptr, nullptr, batch);

    // --- readout: relu(pool @ mw1 + mb1) @ mw2 + mb2 ---
    gemm64<HH, true, true, false><<<(GGR + 63) / 64, 256>>>(
        pool, mw1, mb1, h, nullptr, GGR);
    readout2<<<(GGR * 16 + 255) / 256, 256>>>(h, mw2, mb2, (float*)d_out);
}